// round 8
// baseline (speedup 1.0000x reference)
#include <cuda_runtime.h>
#include <math.h>

#define GD 64
#define SD 32
#define NV (GD*GD*GD)
#define NP (SD*SD*SD)
#define CSTRIDE 10944
#define CH 43

// ---------------- device scratch ----------------
__device__ float g_prob[NV*16];
__device__ float g_hs[8][NV*16];
__device__ float g_h1[NP*16];
__device__ float g_h2[NP*16];
__device__ unsigned char g_occx[NV];
__device__ unsigned char g_pocc[NP];
__device__ unsigned char g_min[NV];
__device__ int g_list_in_c[192*CSTRIDE];
__device__ int g_list_out_c[192*CSTRIDE];
__device__ int g_cnt_in_c[192];
__device__ int g_cnt_out_c[192];

struct K1 {
    const float* w[8]; const float* b[8];
    const float* w20; const float* b20;
    int n_ent;
    int lid[80]; unsigned cand[80]; unsigned char es[80];
};
struct K2 {
    const float* w[8]; const float* b[8];
    int n_ent;
    int lid[32]; unsigned cand[32]; unsigned char es[32];
};

// ---------------- packed f32x2 helpers (sm_100a) ----------------
__device__ __forceinline__ unsigned long long pk2(float v) {
    unsigned long long r;
    asm("mov.b64 %0, {%1, %1};" : "=l"(r) : "f"(v));
    return r;
}
__device__ __forceinline__ unsigned long long pk2(float lo, float hi) {
    unsigned long long r;
    asm("mov.b64 %0, {%1, %2};" : "=l"(r) : "f"(lo), "f"(hi));
    return r;
}
__device__ __forceinline__ void upk2(unsigned long long v, float& lo, float& hi) {
    asm("mov.b64 {%0, %1}, %2;" : "=f"(lo), "=f"(hi) : "l"(v));
}
__device__ __forceinline__ void f2fma(unsigned long long& d, unsigned long long a, unsigned long long b) {
    asm("fma.rn.f32x2 %0, %1, %2, %0;" : "+l"(d) : "l"(a), "l"(b));
}

// 16x16 packed GEMV update: A[8] (16 packed accum) += in_scalar * W_row
__device__ __forceinline__ void gemv16_f2(unsigned long long* A, const float* in,
                                          const float* wrow /*256 floats, cin-major*/) {
    const ulonglong2* wp = (const ulonglong2*)wrow;
    #pragma unroll
    for (int cin=0; cin<16; cin++) {
        unsigned long long v2 = pk2(in[cin]);
        ulonglong2 w01 = wp[cin*4+0];
        ulonglong2 w23 = wp[cin*4+1];
        ulonglong2 w45 = wp[cin*4+2];
        ulonglong2 w67 = wp[cin*4+3];
        f2fma(A[0], v2, w01.x); f2fma(A[1], v2, w01.y);
        f2fma(A[2], v2, w23.x); f2fma(A[3], v2, w23.y);
        f2fma(A[4], v2, w45.x); f2fma(A[5], v2, w45.y);
        f2fma(A[6], v2, w67.x); f2fma(A[7], v2, w67.y);
    }
}

// ---------------- init ----------------
__global__ void k_init(const float* __restrict__ x) {
    int p = blockIdx.x*256 + threadIdx.x;
    if (p < 192) { g_cnt_in_c[p] = 0; g_cnt_out_c[p] = 0; }
    if (p >= NP) return;
    int px = p>>10, py = (p>>5)&31, pz = p&31;
    int bx = px<<1, by = py<<1, bz = pz<<1;
    unsigned char o = 0;
    #pragma unroll
    for (int a=0;a<2;a++)
    #pragma unroll
    for (int b=0;b<2;b++)
    #pragma unroll
    for (int c=0;c<2;c++) {
        int v = ((bx+a)<<12)|((by+b)<<6)|(bz+c);
        unsigned char oc = (x[v] > 0.f) ? 1 : 0;
        g_occx[v] = oc;
        o |= oc;
    }
    g_pocc[p] = o;
}

// ---------------- fused: mask/class-lists/labels + FEL conv1 ----------------
__global__ void k_maskfel1(float* __restrict__ out,
                           const float* __restrict__ wf1, const float* __restrict__ bf1) {
    __shared__ int scnt[384];
    __shared__ int sbase[384];
    __shared__ float swf[432];
    __shared__ float sbf[16];
    int tid = threadIdx.x;
    if (blockIdx.x < 1024) {
        for (int i=tid;i<384;i+=256) scnt[i]=0;
        __syncthreads();
        int v = blockIdx.x*256 + tid;
        int x = v>>12, y = (v>>6)&63, z = v&63;
        const int LUT[8] = {0,5,4,3,4,2,1,5};
        int par = ((x&1)<<2)|((y&1)<<1)|(z&1);
        int gid = LUT[par];
        int mid = ((x>>1)+(y>>1)+(z>>1)) % 3;
        int cls = par*3 + mid;
        bool O = g_pocc[((x>>1)<<10)|((y>>1)<<5)|(z>>1)] != 0;
        bool X = g_occx[v] != 0;
        bool g0 = (gid == 0);

        bool bi[8], bo[8];
        bi[0] = O && g0 && (mid==0);
        bi[1] = (O && g0 && mid==1) || (X && g0 && mid==0);
        bi[2] = (X && g0 && mid<2)  || (O && g0 && mid==2);
        bi[3] = (X && g0)      || (O && gid==1);
        bi[4] = (X && gid<=1)  || (O && gid==2);
        bi[5] = (X && gid<=2)  || (O && gid==3);
        bi[6] = (X && gid<=3)  || (O && gid==4);
        bi[7] = (X && gid<=4)  || (O && gid==5);
        bo[0] = O && g0 && mid==0;
        bo[1] = O && g0 && mid==1;
        bo[2] = O && g0 && mid==2;
        #pragma unroll
        for (int s=3;s<8;s++) bo[s] = O && (gid == s-2);

        unsigned char mb = 0;
        int rin[8], rout[8];
        #pragma unroll
        for (int s=0;s<8;s++) {
            if (bi[s]) { mb |= (1u<<s); rin[s]  = atomicAdd(&scnt[s*24+cls],     1); }
            if (bo[s]) {               rout[s] = atomicAdd(&scnt[192+s*24+cls], 1); }
        }
        g_min[v] = mb;
        __syncthreads();
        for (int i=tid;i<384;i+=256) {
            int c = scnt[i];
            sbase[i] = c ? atomicAdd(i<192 ? &g_cnt_in_c[i] : &g_cnt_out_c[i-192], c) : 0;
        }
        __syncthreads();
        #pragma unroll
        for (int s=0;s<8;s++) {
            if (bi[s]) g_list_in_c [(s*24+cls)*CSTRIDE + sbase[s*24+cls]     + rin[s]]  = v;
            if (bo[s]) g_list_out_c[(s*24+cls)*CSTRIDE + sbase[192+s*24+cls] + rout[s]] = v;
        }
        #pragma unroll
        for (int s=0;s<8;s++) out[(s<<18)+v] = 0.f;
        #pragma unroll
        for (int s=0;s<8;s++) {
            bool lab = (s<3) ? (X && g0 && mid==s) : (X && gid==(s-2));
            out[((8+s)<<18)+v] = lab ? 1.f : 0.f;
        }
    } else {
        for (int i=tid;i<432;i+=256) swf[i]=wf1[i];
        if (tid<16) sbf[tid]=bf1[tid];
        __syncthreads();
        int p = (blockIdx.x-1024)*256 + tid;
        if (!g_pocc[p]) return;
        int px=p>>10, py=(p>>5)&31, pz=p&31;
        float acc[16];
        #pragma unroll
        for (int c=0;c<16;c++) acc[c]=sbf[c];
        for (int dx=-1;dx<=1;dx++){ int nx=px+dx; if ((unsigned)nx>=32u) continue;
        for (int dy=-1;dy<=1;dy++){ int ny=py+dy; if ((unsigned)ny>=32u) continue;
        for (int dz=-1;dz<=1;dz++){ int nz=pz+dz; if ((unsigned)nz>=32u) continue;
            if (!g_pocc[(nx<<10)|(ny<<5)|nz]) continue;
            int d = ((dx+1)*3+(dy+1))*3+(dz+1);
            const float* wr = swf + d*16;
            #pragma unroll
            for (int c=0;c<16;c++) acc[c] += wr[c];
        }}}
        float* o = g_h1 + p*16;
        #pragma unroll
        for (int c=0;c<16;c++) o[c] = fmaxf(acc[c],0.f);
    }
}

// ---------------- FEL conv2 (f32x2) ----------------
__global__ void k_fel2(const float* __restrict__ w, const float* __restrict__ b) {
    __shared__ float sw[27*256];
    int tid = threadIdx.x;
    for (int i=tid;i<6912;i+=blockDim.x) sw[i]=w[i];
    __syncthreads();
    int p = blockIdx.x*blockDim.x + tid;
    if (p >= NP) return;
    if (!g_pocc[p]) return;
    unsigned long long A[8];
    #pragma unroll
    for (int j=0;j<8;j++) A[j] = pk2(b[2*j], b[2*j+1]);
    int px=p>>10, py=(p>>5)&31, pz=p&31;
    for (int dx=-1;dx<=1;dx++){ int nx=px+dx; if ((unsigned)nx>=32u) continue;
    for (int dy=-1;dy<=1;dy++){ int ny=py+dy; if ((unsigned)ny>=32u) continue;
    for (int dz=-1;dz<=1;dz++){ int nz=pz+dz; if ((unsigned)nz>=32u) continue;
        int nv = (nx<<10)|(ny<<5)|nz;
        if (!g_pocc[nv]) continue;
        int d = ((dx+1)*3+(dy+1))*3+(dz+1);
        const float4* hp4 = (const float4*)(g_h1 + nv*16);
        float4 h0=hp4[0], h1=hp4[1], h2=hp4[2], h3=hp4[3];
        float in[16] = {h0.x,h0.y,h0.z,h0.w, h1.x,h1.y,h1.z,h1.w,
                        h2.x,h2.y,h2.z,h2.w, h3.x,h3.y,h3.z,h3.w};
        gemv16_f2(A, in, sw + d*256);
    }}}
    float* o = g_h2 + p*16;
    #pragma unroll
    for (int j=0;j<8;j++) upk2(A[j], o[2*j], o[2*j+1]);
}

// ---------------- generative upsample (f32x2) ----------------
__global__ void k_up(const float* __restrict__ wup, const float* __restrict__ bup) {
    __shared__ float sw[8*256];
    __shared__ float sb[16];
    int tid = threadIdx.x;
    for (int i=tid;i<2048;i+=blockDim.x) sw[i]=wup[i];
    if (tid<16) sb[tid]=bup[tid];
    __syncthreads();
    int v = blockIdx.x*blockDim.x + tid;
    if (v >= NV) return;
    int x=v>>12, y=(v>>6)&63, z=v&63;
    int p = ((x>>1)<<10)|((y>>1)<<5)|(z>>1);
    float* po = g_prob + v*16;
    if (!g_pocc[p]) {
        #pragma unroll
        for (int c=0;c<16;c++) po[c]=0.f;
        return;
    }
    int o = ((x&1)<<2)|((y&1)<<1)|(z&1);
    unsigned long long A[8];
    #pragma unroll
    for (int j=0;j<8;j++) A[j] = pk2(sb[2*j], sb[2*j+1]);
    const float4* hp4 = (const float4*)(g_h2 + p*16);
    float4 h0=hp4[0], h1=hp4[1], h2=hp4[2], h3=hp4[3];
    float in[16] = {h0.x,h0.y,h0.z,h0.w, h1.x,h1.y,h1.z,h1.w,
                    h2.x,h2.y,h2.z,h2.w, h3.x,h3.y,h3.z,h3.w};
    gemv16_f2(A, in, sw + o*256);
    #pragma unroll
    for (int j=0;j<8;j++) upk2(A[j], po[2*j], po[2*j+1]);
}

// ---------------- conv1: class-uniform blocks, predicated taps, f32x2 ----------------
__global__ void __launch_bounds__(256) k_conv1_all(K1 P, float* __restrict__ out) {
    int e = blockIdx.x / CH, ch = blockIdx.x % CH;
    int s = P.es[e];
    int lid = P.lid[e];
    int cnt = g_cnt_in_c[lid];
    if (ch*256 >= cnt) return;
    __shared__ float sw[6944];
    int tid = threadIdx.x;

    if (s == 0) {
        if (tid < 256) sw[tid] = P.w[0][13*256 + tid];
        if (tid < 16)  sw[6912+tid] = P.w20[13*16 + tid];
        if (tid < 16)  sw[6928+tid] = P.b[0][tid];
        __syncthreads();
        int idx = ch*256 + tid;
        if (idx >= cnt) return;
        int v = g_list_in_c[lid*CSTRIDE + idx];
        const float4* pin = (const float4*)(g_prob + v*16);
        float4 i0=pin[0], i1=pin[1], i2=pin[2], i3=pin[3];
        float in[16] = {i0.x,i0.y,i0.z,i0.w, i1.x,i1.y,i1.z,i1.w,
                        i2.x,i2.y,i2.z,i2.w, i3.x,i3.y,i3.z,i3.w};
        unsigned long long A[8];
        #pragma unroll
        for (int j=0;j<8;j++) A[j] = pk2(sw[6928+2*j], sw[6928+2*j+1]);
        gemv16_f2(A, in, sw);
        float acc = P.b20[0];
        #pragma unroll
        for (int j=0;j<8;j++) {
            float lo,hi; upk2(A[j], lo, hi);
            acc += fmaxf(lo,0.f)*sw[6912+2*j] + fmaxf(hi,0.f)*sw[6912+2*j+1];
        }
        out[v] = 1.f/(1.f + expf(-acc));
        return;
    }

    bool is5 = (s==1 || s==2);
    const float* w = P.w[s];
    if (is5) {
        for (int i=tid;i<6912;i+=256) {
            int t=i>>8, c=i&255;
            int a=t/9, bb=(t/3)%3, cc=t%3;
            sw[i] = w[(((2*a)*5+2*bb)*5+2*cc)*256 + c];
        }
    } else {
        for (int i=tid;i<6912;i+=256) sw[i]=w[i];
    }
    __syncthreads();
    int idx = ch*256 + tid;
    if (idx >= cnt) return;
    int v = g_list_in_c[lid*CSTRIDE + idx];
    int x=v>>12, y=(v>>6)&63, z=v&63;
    int sc = is5 ? 2 : 1;
    unsigned m = P.cand[e];
    const float* bb = P.b[s];
    unsigned long long A[8];
    #pragma unroll
    for (int j=0;j<8;j++) A[j] = pk2(bb[2*j], bb[2*j+1]);
    while (m) {
        int t = __ffs(m)-1; m &= m-1;
        int nx = x + sc*(t/9-1), ny = y + sc*((t/3)%3-1), nz = z + sc*(t%3-1);
        bool inb = ((unsigned)(nx|ny|nz) < 64u);
        int nvc = ((nx&63)<<12)|((ny&63)<<6)|(nz&63);
        float sel = (inb && ((g_min[nvc]>>s)&1)) ? 1.f : 0.f;
        const float4* pin = (const float4*)(g_prob + nvc*16);
        float4 i0=pin[0], i1=pin[1], i2=pin[2], i3=pin[3];
        float in[16] = {sel*i0.x,sel*i0.y,sel*i0.z,sel*i0.w, sel*i1.x,sel*i1.y,sel*i1.z,sel*i1.w,
                        sel*i2.x,sel*i2.y,sel*i2.z,sel*i2.w, sel*i3.x,sel*i3.y,sel*i3.z,sel*i3.w};
        gemv16_f2(A, in, sw + t*256);
    }
    float* ph = &g_hs[s][v*16];
    #pragma unroll
    for (int j=0;j<8;j++) {
        float lo,hi; upk2(A[j], lo, hi);
        ph[2*j]   = fmaxf(lo,0.f);
        ph[2*j+1] = fmaxf(hi,0.f);
    }
}

// ---------------- conv2: class-uniform blocks, predicated taps, f32x2 ----------------
__global__ void __launch_bounds__(256) k_conv2_all(K2 P, float* __restrict__ out) {
    int e = blockIdx.x / CH, ch = blockIdx.x % CH;
    int s = P.es[e];
    int lid = P.lid[e];
    int cnt = g_cnt_out_c[lid];
    if (ch*256 >= cnt) return;
    __shared__ float sw[432];
    int tid = threadIdx.x;
    bool is5 = (s==1 || s==2);
    const float* w = P.w[s];
    if (is5) {
        for (int i=tid;i<432;i+=256) {
            int t=i>>4, c=i&15;
            int a=t/9, bb=(t/3)%3, cc=t%3;
            sw[i] = w[(((2*a)*5+2*bb)*5+2*cc)*16 + c];
        }
    } else {
        for (int i=tid;i<432;i+=256) sw[i]=w[i];
    }
    __syncthreads();
    int idx = ch*256 + tid;
    if (idx >= cnt) return;
    int v = g_list_out_c[lid*CSTRIDE + idx];
    int x=v>>12, y=(v>>6)&63, z=v&63;
    int sc = is5 ? 2 : 1;
    unsigned m = P.cand[e];
    const float* hbase = g_hs[s];
    float acc = P.b[s][0];
    while (m) {
        int t = __ffs(m)-1; m &= m-1;
        int nx = x + sc*(t/9-1), ny = y + sc*((t/3)%3-1), nz = z + sc*(t%3-1);
        bool inb = ((unsigned)(nx|ny|nz) < 64u);
        int nvc = ((nx&63)<<12)|((ny&63)<<6)|(nz&63);
        float sel = (inb && ((g_min[nvc]>>s)&1)) ? 1.f : 0.f;
        const float4* pc = (const float4*)(hbase + nvc*16);
        float4 c0=pc[0], c1=pc[1], c2=pc[2], c3=pc[3];
        const ulonglong2* wr = (const ulonglong2*)(sw + t*16);
        ulonglong2 wa = wr[0], wb = wr[1], wc = wr[2], wd = wr[3];
        unsigned long long d2a = 0ull, d2b = 0ull;
        f2fma(d2a, pk2(c0.x,c0.y), wa.x);
        f2fma(d2b, pk2(c0.z,c0.w), wa.y);
        f2fma(d2a, pk2(c1.x,c1.y), wb.x);
        f2fma(d2b, pk2(c1.z,c1.w), wb.y);
        f2fma(d2a, pk2(c2.x,c2.y), wc.x);
        f2fma(d2b, pk2(c2.z,c2.w), wc.y);
        f2fma(d2a, pk2(c3.x,c3.y), wd.x);
        f2fma(d2b, pk2(c3.z,c3.w), wd.y);
        float la,ha,lb,hb;
        upk2(d2a, la, ha);
        upk2(d2b, lb, hb);
        acc += sel*((la+ha)+(lb+hb));
    }
    out[(s<<18)+v] = 1.f/(1.f + expf(-acc));
}

// ---------------- host-side class/LUT construction ----------------
static const int GIDH[8] = {0,5,4,3,4,2,1,5};

static bool cand_in(int s, int par, int mid) {
    int gid = GIDH[par];
    if (s==0) return gid==0 && mid==0;
    if (s==1) return gid==0 && mid<2;
    if (s==2) return gid==0;
    return gid <= s-2;
}

static int middelta(int pc, int d) {
    if (d==-2) return -1;
    if (d== 2) return  1;
    if (d== 0) return  0;
    if (pc==0) return d==-1 ? -1 : 0;
    return d==1 ? 1 : 0;
}

static unsigned mask3(int s, int par, int mid) {
    unsigned m=0;
    for (int t=0;t<27;t++) {
        int dx=t/9-1, dy=(t/3)%3-1, dz=t%3-1;
        int pn = par ^ ((((dx&1))<<2)|(((dy&1))<<1)|(dz&1));
        int dm = middelta((par>>2)&1,dx)+middelta((par>>1)&1,dy)+middelta(par&1,dz);
        int mn = ((mid+dm)%3+3)%3;
        if (cand_in(s,pn,mn)) m |= 1u<<t;
    }
    return m;
}

static unsigned mask5(int s, int mid) {
    unsigned m=0;
    for (int t=0;t<27;t++) {
        int dx=2*(t/9-1), dy=2*((t/3)%3-1), dz=2*(t%3-1);
        int dm=(dx+dy+dz)/2;
        int mn=((mid+dm)%3+3)%3;
        if (cand_in(s,0,mn)) m |= 1u<<t;
    }
    return m;
}

static bool out_class(int s, int par, int mid) {
    int gid = GIDH[par];
    if (s<3) return gid==0 && mid==s;
    return gid == s-2;
}

// ---------------- launch ----------------
extern "C" void kernel_launch(void* const* d_in, const int* in_sizes, int n_in,
                              void* d_out, int out_size) {
    const float* x      = (const float*)d_in[0];
    const float* w_fel1 = (const float*)d_in[3];
    const float* b_fel1 = (const float*)d_in[4];
    const float* w_fel2 = (const float*)d_in[5];
    const float* b_fel2 = (const float*)d_in[6];
    const float* w_up   = (const float*)d_in[7];
    const float* b_up   = (const float*)d_in[8];
    const float* wc1    = (const float*)d_in[9];
    const float* bc1    = (const float*)d_in[10];
    const float* wc2    = (const float*)d_in[11];
    const float* bc2    = (const float*)d_in[12];
    const float* wl1    = (const float*)d_in[13];
    const float* bl1    = (const float*)d_in[14];
    const float* wl2    = (const float*)d_in[15];
    const float* bl2    = (const float*)d_in[16];
    float* out = (float*)d_out;

    K1 p1; K2 p2;
    for (int s=0;s<8;s++) {
        if (s==1 || s==2) {
            p1.w[s] = wl1 + (s-1)*125*256; p1.b[s] = bl1 + (s-1)*16;
            p2.w[s] = wl2 + (s-1)*125*16;  p2.b[s] = bl2 + (s-1);
        } else {
            int k = (s==0) ? 0 : (s-2);
            p1.w[s] = wc1 + k*27*256; p1.b[s] = bc1 + k*16;
            p2.w[s] = wc2 + k*27*16;  p2.b[s] = bc2 + k;
        }
    }
    p1.w20 = wc2; p1.b20 = bc2;

    int n1 = 0;
    for (int s=0;s<8;s++)
        for (int par=0;par<8;par++)
            for (int mid=0;mid<3;mid++)
                if (cand_in(s,par,mid)) {
                    p1.es[n1]  = (unsigned char)s;
                    p1.lid[n1] = s*24 + par*3 + mid;
                    p1.cand[n1] = (s==0) ? (1u<<13)
                                : (s<=2) ? mask5(s,mid)
                                         : mask3(s,par,mid);
                    n1++;
                }
    p1.n_ent = n1;

    int n2 = 0;
    for (int s=1;s<8;s++)
        for (int par=0;par<8;par++)
            for (int mid=0;mid<3;mid++)
                if (out_class(s,par,mid)) {
                    p2.es[n2]  = (unsigned char)s;
                    p2.lid[n2] = s*24 + par*3 + mid;
                    p2.cand[n2] = (s<=2) ? mask5(s,mid) : mask3(s,par,mid);
                    n2++;
                }
    p2.n_ent = n2;

    k_init<<<128,256>>>(x);
    k_maskfel1<<<1152,256>>>(out, w_fel1, b_fel1);
    k_fel2<<<128,256>>>(w_fel2, b_fel2);
    k_up<<<1024,256>>>(w_up, b_up);
    k_conv1_all<<<n1*CH,256>>>(p1, out);
    k_conv2_all<<<n2*CH,256>>>(p2, out);
}